// round 6
// baseline (speedup 1.0000x reference)
#include <cuda_runtime.h>
#include <cuda_bf16.h>
#include <cstdint>

// Problem constants (fixed by the dataset)
#define Bn 4
#define Nn 10000
#define Dn 64
#define Cn 2
#define En 160000
#define EPSc 1e-10f
#define BCn (Bn * Cn)
#define CAP 64           // bucket capacity per destination node (mean count = 16)

// Static scratch (no allocation allowed)
__device__ float  g_s1[BCn * Nn];              // node scores (dst half)
__device__ float  g_s2[BCn * Nn];              // node scores (src half)
__device__ float  g_denom[BCn * Nn];           // segment sum of e by idx0
__device__ int    g_cnt[BCn * Nn];             // edges per destination node
__device__ float2 g_bucket[(size_t)BCn * Nn * CAP];  // (idx1 bits, e) slots (41 MB)

__device__ __forceinline__ float fast_tanh(float x) {
    float y;
    asm("tanh.approx.f32 %0, %1;" : "=f"(y) : "f"(x));
    return y;
}
__device__ __forceinline__ float fast_sigmoid(float x) {
    return 0.5f * fast_tanh(0.5f * x) + 0.5f;
}

// ---------------------------------------------------------------------------
// K0: zero cnt only (denom is now computed by overwrite in denom_kernel)
__global__ void zero_kernel() {
    int t = blockIdx.x * blockDim.x + threadIdx.x;
    if (t < BCn * Nn) g_cnt[t] = 0;
}

// ---------------------------------------------------------------------------
// K1: per-node scores. One warp per (b, n).
__global__ void scores_kernel(const float* __restrict__ x,
                              const float* __restrict__ wa) {
    int w = (blockIdx.x * blockDim.x + threadIdx.x) >> 5;
    int lane = threadIdx.x & 31;
    if (w >= Bn * Nn) return;
    int b = w / Nn;
    int n = w - b * Nn;

    float2 xv = reinterpret_cast<const float2*>(x + (size_t)(b * Nn + n) * Dn)[lane];

#pragma unroll
    for (int c = 0; c < Cn; c++) {
        float2 w1 = reinterpret_cast<const float2*>(wa + c * 2 * Dn)[lane];
        float2 w2 = reinterpret_cast<const float2*>(wa + c * 2 * Dn + Dn)[lane];
        float p1 = xv.x * w1.x + xv.y * w1.y;
        float p2 = xv.x * w2.x + xv.y * w2.y;
#pragma unroll
        for (int o = 16; o; o >>= 1) {
            p1 += __shfl_xor_sync(0xffffffffu, p1, o);
            p2 += __shfl_xor_sync(0xffffffffu, p2, o);
        }
        if (lane == 0) {
            g_s1[(b * Cn + c) * Nn + n] = p1;
            g_s2[(b * Cn + c) * Nn + n] = p2;
        }
    }
}

// ---------------------------------------------------------------------------
// K2: edge pass: exp + bucket placement. Only ONE atomic (the cursor).
__global__ void edge_kernel(const int2* __restrict__ ep) {
    int t = blockIdx.x * blockDim.x + threadIdx.x;
    if (t >= BCn * En) return;
    int bc = t / En;
    int2 p = ep[t];                         // p.x = idx0 (dst), p.y = idx1 (src)
    float sc = g_s1[bc * Nn + p.y] + g_s2[bc * Nn + p.x];
    sc = sc >= 0.f ? sc : 0.2f * sc;        // leaky_relu(0.2)
    float ev = __expf(sc);
    int node = bc * Nn + p.x;
    int pos = atomicAdd(&g_cnt[node], 1);
    if (pos < CAP)                          // overflow prob ~1e-24; safety clamp
        g_bucket[((size_t)node << 6) + pos] = make_float2(__int_as_float(p.y), ev);
}

// ---------------------------------------------------------------------------
// K2b: denom[node] = sum of e over its bucket. 16 lanes per node, no atomics.
__global__ void denom_kernel() {
    int t = blockIdx.x * blockDim.x + threadIdx.x;   // 1.28M threads
    int node = t >> 4;
    if (node >= BCn * Nn) return;
    int seg = t & 15;
    int cnt = min(g_cnt[node], CAP);
    const float2* pairs = g_bucket + ((size_t)node << 6);
    float s = 0.f;
#pragma unroll
    for (int j = 0; j < 4; j++) {
        int i = seg + j * 16;
        if (i < cnt) s += pairs[i].y;
    }
#pragma unroll
    for (int o = 8; o; o >>= 1)
        s += __shfl_xor_sync(0xffffffffu, s, o);     // stays within 16-lane half
    if (seg == 0) g_denom[node] = s;
}

// ---------------------------------------------------------------------------
// K3: gather + alpha division + sigmoid. 16 lanes per (b, n).
// Inner loop is a compile-time 16 iterations (padded with alpha=0, i1=0) so
// ptxas can batch all 16 LDG.128s -> per-thread MLP ~16.
__global__ void gather_kernel(const float* __restrict__ x,
                              float* __restrict__ out) {
    int t = blockIdx.x * blockDim.x + threadIdx.x;   // 640,000 threads
    int g = t >> 4;                                  // (b, n) group
    if (g >= Bn * Nn) return;
    int seg = t & 15;
    int lane = threadIdx.x & 31;
    unsigned mask = (lane < 16) ? 0x0000ffffu : 0xffff0000u;
    int halfbase = lane & 16;
    int b = g / Nn;
    int n = g - b * Nn;
    const float4* x4 = reinterpret_cast<const float4*>(x) + (size_t)b * Nn * 16;

    float4 res[Cn];
#pragma unroll
    for (int c = 0; c < Cn; c++) {
        int bc = b * Cn + c;
        int node = bc * Nn + n;
        int cnt = min(g_cnt[node], CAP);
        const float2* pairs = g_bucket + ((size_t)node << 6);
        const float* den_base = g_denom + bc * Nn;

        float4 acc0 = make_float4(0.f, 0.f, 0.f, 0.f);
        float4 acc1 = make_float4(0.f, 0.f, 0.f, 0.f);

        for (int base = 0; base < cnt; base += 16) {
            float alpha_mine = 0.f;
            int i1_mine = 0;
            if (base + seg < cnt) {
                float2 pr = pairs[base + seg];
                i1_mine = __float_as_int(pr.x);
                alpha_mine = __fdividef(pr.y, den_base[i1_mine] + EPSc);
            }
#pragma unroll
            for (int k = 0; k < 16; k++) {
                float al = __shfl_sync(mask, alpha_mine, halfbase + k);
                int i1 = __shfl_sync(mask, i1_mine, halfbase + k);
                float4 xv = x4[(size_t)i1 * 16 + seg];
                if (k & 1) {
                    acc1.x = fmaf(al, xv.x, acc1.x);
                    acc1.y = fmaf(al, xv.y, acc1.y);
                    acc1.z = fmaf(al, xv.z, acc1.z);
                    acc1.w = fmaf(al, xv.w, acc1.w);
                } else {
                    acc0.x = fmaf(al, xv.x, acc0.x);
                    acc0.y = fmaf(al, xv.y, acc0.y);
                    acc0.z = fmaf(al, xv.z, acc0.z);
                    acc0.w = fmaf(al, xv.w, acc0.w);
                }
            }
        }
        res[c] = make_float4(acc0.x + acc1.x, acc0.y + acc1.y,
                             acc0.z + acc1.z, acc0.w + acc1.w);
    }

    float4 o;
    o.x = fast_sigmoid(res[0].x) + fast_sigmoid(res[1].x);
    o.y = fast_sigmoid(res[0].y) + fast_sigmoid(res[1].y);
    o.z = fast_sigmoid(res[0].z) + fast_sigmoid(res[1].z);
    o.w = fast_sigmoid(res[0].w) + fast_sigmoid(res[1].w);
    reinterpret_cast<float4*>(out)[(size_t)g * 16 + seg] = o;
}

// ---------------------------------------------------------------------------
extern "C" void kernel_launch(void* const* d_in, const int* in_sizes, int n_in,
                              void* d_out, int out_size) {
    const float* x  = (const float*)d_in[0];   // (B, N, D) f32
    const int2*  ep = (const int2*) d_in[1];   // (B, C, E, 2) i32 -> int2 pairs
    const float* wa = (const float*)d_in[2];   // (C, 2D, 1) f32
    float* out = (float*)d_out;                // (B, N, D) f32

    zero_kernel<<<(BCn * Nn + 255) / 256, 256>>>();
    scores_kernel<<<(Bn * Nn * 32 + 255) / 256, 256>>>(x, wa);
    edge_kernel<<<(BCn * En + 255) / 256, 256>>>(ep);
    denom_kernel<<<(BCn * Nn * 16 + 255) / 256, 256>>>();
    gather_kernel<<<(Bn * Nn * 16 + 255) / 256, 256>>>(x, out);
}

// round 7
// speedup vs baseline: 1.0527x; 1.0527x over previous
#include <cuda_runtime.h>
#include <cuda_bf16.h>
#include <cstdint>

// Problem constants (fixed by the dataset)
#define Bn 4
#define Nn 10000
#define Dn 64
#define Cn 2
#define En 160000
#define EPSc 1e-10f
#define BCn (Bn * Cn)
#define CAP 64           // bucket capacity per destination node (mean count = 16)

// Static scratch (no allocation allowed)
__device__ float  g_s1[BCn * Nn];              // node scores (dst half)
__device__ float  g_s2[BCn * Nn];              // node scores (src half)
__device__ float  g_denom[BCn * Nn];           // segment sum of e by idx0
__device__ int    g_cnt[BCn * Nn];             // edges per destination node
__device__ float2 g_bucket[(size_t)BCn * Nn * CAP];  // (idx1 bits, e) slots (41 MB)

__device__ __forceinline__ float fast_tanh(float x) {
    float y;
    asm("tanh.approx.f32 %0, %1;" : "=f"(y) : "f"(x));
    return y;
}
__device__ __forceinline__ float fast_sigmoid(float x) {
    return 0.5f * fast_tanh(0.5f * x) + 0.5f;
}

// ---------------------------------------------------------------------------
// K0: zero denom + cnt (graph replays re-run everything)
__global__ void zero_kernel() {
    int t = blockIdx.x * blockDim.x + threadIdx.x;
    if (t < BCn * Nn) {
        g_denom[t] = 0.f;
        g_cnt[t] = 0;
    }
}

// ---------------------------------------------------------------------------
// K1: per-node scores. One warp per (b, n).
__global__ void scores_kernel(const float* __restrict__ x,
                              const float* __restrict__ wa) {
    int w = (blockIdx.x * blockDim.x + threadIdx.x) >> 5;
    int lane = threadIdx.x & 31;
    if (w >= Bn * Nn) return;
    int b = w / Nn;
    int n = w - b * Nn;

    float2 xv = reinterpret_cast<const float2*>(x + (size_t)(b * Nn + n) * Dn)[lane];

#pragma unroll
    for (int c = 0; c < Cn; c++) {
        float2 w1 = reinterpret_cast<const float2*>(wa + c * 2 * Dn)[lane];
        float2 w2 = reinterpret_cast<const float2*>(wa + c * 2 * Dn + Dn)[lane];
        float p1 = xv.x * w1.x + xv.y * w1.y;
        float p2 = xv.x * w2.x + xv.y * w2.y;
#pragma unroll
        for (int o = 16; o; o >>= 1) {
            p1 += __shfl_xor_sync(0xffffffffu, p1, o);
            p2 += __shfl_xor_sync(0xffffffffu, p2, o);
        }
        if (lane == 0) {
            g_s1[(b * Cn + c) * Nn + n] = p1;
            g_s2[(b * Cn + c) * Nn + n] = p2;
        }
    }
}

// ---------------------------------------------------------------------------
// K2: single edge pass: exp, denom accumulation, and bucket placement.
// pos = atomicAdd(cnt) doubles as the placement cursor and the final count.
__global__ void edge_kernel(const int2* __restrict__ ep) {
    int t = blockIdx.x * blockDim.x + threadIdx.x;
    if (t >= BCn * En) return;
    int bc = t / En;
    int2 p = ep[t];                         // p.x = idx0 (dst), p.y = idx1 (src)
    float sc = g_s1[bc * Nn + p.y] + g_s2[bc * Nn + p.x];
    sc = sc >= 0.f ? sc : 0.2f * sc;        // leaky_relu(0.2)
    float ev = __expf(sc);
    int node = bc * Nn + p.x;
    atomicAdd(&g_denom[node], ev);
    int pos = atomicAdd(&g_cnt[node], 1);
    if (pos < CAP)                          // overflow prob ~1e-24; safety clamp
        g_bucket[((size_t)node << 6) + pos] = make_float2(__int_as_float(p.y), ev);
}

// ---------------------------------------------------------------------------
// K3: gather + alpha division + sigmoid. 16 lanes per (b, n).
// Inner loop is a compile-time 16 iterations (padded with alpha=0, i1=0) so
// ptxas can batch all 16 LDG.128s -> per-thread MLP ~16.
__global__ void gather_kernel(const float* __restrict__ x,
                              float* __restrict__ out) {
    int t = blockIdx.x * blockDim.x + threadIdx.x;   // 640,000 threads
    int g = t >> 4;                                  // (b, n) group
    if (g >= Bn * Nn) return;
    int seg = t & 15;
    int lane = threadIdx.x & 31;
    unsigned mask = (lane < 16) ? 0x0000ffffu : 0xffff0000u;
    int halfbase = lane & 16;
    int b = g / Nn;
    int n = g - b * Nn;
    const float4* x4 = reinterpret_cast<const float4*>(x) + (size_t)b * Nn * 16;

    float4 res[Cn];
#pragma unroll
    for (int c = 0; c < Cn; c++) {
        int bc = b * Cn + c;
        int node = bc * Nn + n;
        int cnt = min(g_cnt[node], CAP);
        const float2* pairs = g_bucket + ((size_t)node << 6);
        const float* den_base = g_denom + bc * Nn;

        float4 acc0 = make_float4(0.f, 0.f, 0.f, 0.f);
        float4 acc1 = make_float4(0.f, 0.f, 0.f, 0.f);

        for (int base = 0; base < cnt; base += 16) {
            float alpha_mine = 0.f;
            int i1_mine = 0;
            if (base + seg < cnt) {
                float2 pr = pairs[base + seg];
                i1_mine = __float_as_int(pr.x);
                alpha_mine = __fdividef(pr.y, den_base[i1_mine] + EPSc);
            }
#pragma unroll
            for (int k = 0; k < 16; k++) {
                float al = __shfl_sync(mask, alpha_mine, halfbase + k);
                int i1 = __shfl_sync(mask, i1_mine, halfbase + k);
                float4 xv = x4[(size_t)i1 * 16 + seg];
                if (k & 1) {
                    acc1.x = fmaf(al, xv.x, acc1.x);
                    acc1.y = fmaf(al, xv.y, acc1.y);
                    acc1.z = fmaf(al, xv.z, acc1.z);
                    acc1.w = fmaf(al, xv.w, acc1.w);
                } else {
                    acc0.x = fmaf(al, xv.x, acc0.x);
                    acc0.y = fmaf(al, xv.y, acc0.y);
                    acc0.z = fmaf(al, xv.z, acc0.z);
                    acc0.w = fmaf(al, xv.w, acc0.w);
                }
            }
        }
        res[c] = make_float4(acc0.x + acc1.x, acc0.y + acc1.y,
                             acc0.z + acc1.z, acc0.w + acc1.w);
    }

    float4 o;
    o.x = fast_sigmoid(res[0].x) + fast_sigmoid(res[1].x);
    o.y = fast_sigmoid(res[0].y) + fast_sigmoid(res[1].y);
    o.z = fast_sigmoid(res[0].z) + fast_sigmoid(res[1].z);
    o.w = fast_sigmoid(res[0].w) + fast_sigmoid(res[1].w);
    reinterpret_cast<float4*>(out)[(size_t)g * 16 + seg] = o;
}

// ---------------------------------------------------------------------------
extern "C" void kernel_launch(void* const* d_in, const int* in_sizes, int n_in,
                              void* d_out, int out_size) {
    const float* x  = (const float*)d_in[0];   // (B, N, D) f32
    const int2*  ep = (const int2*) d_in[1];   // (B, C, E, 2) i32 -> int2 pairs
    const float* wa = (const float*)d_in[2];   // (C, 2D, 1) f32
    float* out = (float*)d_out;                // (B, N, D) f32

    zero_kernel<<<(BCn * Nn + 255) / 256, 256>>>();
    scores_kernel<<<(Bn * Nn * 32 + 255) / 256, 256>>>(x, wa);
    edge_kernel<<<(BCn * En + 255) / 256, 256>>>(ep);
    gather_kernel<<<(Bn * Nn * 16 + 255) / 256, 256>>>(x, out);
}